// round 1
// baseline (speedup 1.0000x reference)
#include <cuda_runtime.h>
#include <cfloat>

#define BHn   64
#define TQn   1024
#define TKn   1024
#define DKn   64
#define QT    16      // queries per block
#define KTILE 128     // key tile rows staged in smem
#define NTHR  256
#define KST   66      // padded row stride (floats) for K/V/Q tiles  (66 mod 32 = 2 -> conflict-free)
#define SCST  1040    // padded row stride (floats) for score tile   (1040 mod 32 = 16 -> disjoint halves)

#define SMEM_BYTES ((QT*KST + KTILE*KST + QT*SCST) * 4)   // 104576 B

// ---------------------------------------------------------------------------
// mask dtype auto-detect: 1 if mask elements are 1-byte (bool/int8), else 0
// (int32 0/1 data has all bytes at i%4!=0 equal to zero)
// ---------------------------------------------------------------------------
__device__ int g_mask_narrow;

__global__ void detect_mask_kernel(const unsigned int* __restrict__ mw) {
    __shared__ int found;
    if (threadIdx.x == 0) found = 0;
    __syncthreads();
    int local = 0;
    // scan first 64KB (= full bool buffer, or first quarter of an int32 buffer)
    for (int i = threadIdx.x; i < (BHn * TKn) / 4; i += blockDim.x) {
        if (mw[i] & 0xFFFFFF00u) local = 1;
    }
    if (local) atomicOr(&found, 1);
    __syncthreads();
    if (threadIdx.x == 0) g_mask_narrow = found;
}

// packed dual-fp32 FMA (ptxas never emits FFMA2 from C++; PTX f32x2 is required)
__device__ __forceinline__ float2 ffma2(float2 a, float2 b, float2 c) {
    float2 d;
    asm("fma.rn.f32x2 %0, %1, %2, %3;"
        : "=l"(reinterpret_cast<unsigned long long&>(d))
        : "l"(reinterpret_cast<unsigned long long&>(a)),
          "l"(reinterpret_cast<unsigned long long&>(b)),
          "l"(reinterpret_cast<unsigned long long&>(c)));
    return d;
}

// ---------------------------------------------------------------------------
// main attention kernel: one block = (16 queries) x (one bh head)
// ---------------------------------------------------------------------------
extern "C" __global__ void __launch_bounds__(NTHR, 2)
attn_fp32x2_kernel(const float* __restrict__ Q, const float* __restrict__ K,
                   const float* __restrict__ V, const unsigned char* __restrict__ Mb,
                   const int* __restrict__ pHA, const int* __restrict__ pNH,
                   float* __restrict__ Out, int write_w)
{
    extern __shared__ float sm[];
    float* qsh  = sm;                         // [QT][KST]
    float* kvsh = sm + QT * KST;              // [KTILE][KST]
    float* scsh = kvsh + KTILE * KST;         // [QT][SCST]

    const int t  = threadIdx.x;
    const int bh = blockIdx.y;
    const int q0 = blockIdx.x * QT;

    const int nh = pNH[0];                    // low 32 bits: correct for i32 or LE i64
    const int ha = pHA[0];

    float* Wout      = Out + (size_t)BHn * TQn * DKn;
    float* wrow_base = Wout + ((size_t)bh * TQn + q0) * TKn;
    float* orow_base = Out  + ((size_t)bh * TQn + q0) * DKn;

    // ---- head ablation: weights and output are exactly zero ----
    if (nh > 0 && (bh % nh) == ha) {
        float4 z = make_float4(0.f, 0.f, 0.f, 0.f);
        if (write_w) {
            float4* w4 = (float4*)wrow_base;
            #pragma unroll 4
            for (int i = t; i < QT * TKn / 4; i += NTHR) w4[i] = z;
        }
        float4* o4 = (float4*)orow_base;
        for (int i = t; i < QT * DKn / 4; i += NTHR) o4[i] = z;
        return;
    }

    const int shift = g_mask_narrow ? 0 : 2;
    const unsigned char* mrow = Mb + (((size_t)bh * TKn) << shift);

    // ---- load Q tile: 16x64 floats = 512 float2, 2 per thread ----
    {
        const float2* Qg = (const float2*)(Q + ((size_t)bh * TQn + q0) * DKn);
        #pragma unroll
        for (int i = 0; i < 2; i++) {
            int idx = t + i * NTHR;          // 0..511
            int r = idx >> 5, c = idx & 31;  // 32 float2 per row
            float2 v = Qg[(size_t)r * 32 + c];
            *(float2*)&qsh[r * KST + 2 * c] = v;
        }
    }

    const int ql  = t >> 4;   // 0..15 : query row owned in phase A
    const int kl0 = t & 15;   // key lane

    // ================= Phase A: scores = QK^T / 8, masked =================
    for (int kt = 0; kt < TKn / KTILE; kt++) {
        __syncthreads();   // previous tile consumers done
        const float2* Kg = (const float2*)(K + ((size_t)bh * TKn + kt * KTILE) * DKn);
        #pragma unroll
        for (int i = 0; i < 16; i++) {
            int idx = t + i * NTHR;          // 0..4095
            int r = idx >> 5, c = idx & 31;
            float2 v = Kg[(size_t)r * 32 + c];
            *(float2*)&kvsh[r * KST + 2 * c] = v;
        }
        __syncthreads();

        float2 acc[8];
        #pragma unroll
        for (int j = 0; j < 8; j++) acc[j] = make_float2(0.f, 0.f);
        #pragma unroll
        for (int d2 = 0; d2 < 32; d2++) {
            float2 q2 = *(float2*)&qsh[ql * KST + 2 * d2];
            #pragma unroll
            for (int j = 0; j < 8; j++) {
                float2 k2 = *(float2*)&kvsh[(kl0 + 16 * j) * KST + 2 * d2];
                acc[j] = ffma2(q2, k2, acc[j]);
            }
        }
        const int kb = kt * KTILE;
        #pragma unroll
        for (int j = 0; j < 8; j++) {
            int k = kb + kl0 + 16 * j;
            unsigned char m = mrow[(size_t)k << shift];
            float s = (acc[j].x + acc[j].y) * 0.125f;   // 1/sqrt(64)
            scsh[ql * SCST + k] = m ? s : -FLT_MAX;     // == jnp.finfo(f32).min
        }
    }
    __syncthreads();

    // ================= softmax (16 lanes per query row) =================
    float mx = -FLT_MAX;
    #pragma unroll 4
    for (int i = 0; i < TKn / 16; i++)
        mx = fmaxf(mx, scsh[ql * SCST + kl0 + 16 * i]);
    #pragma unroll
    for (int off = 8; off > 0; off >>= 1)
        mx = fmaxf(mx, __shfl_xor_sync(0xffffffffu, mx, off, 16));

    float ssum = 0.f;
    #pragma unroll 4
    for (int i = 0; i < TKn / 16; i++) {
        int k = kl0 + 16 * i;
        float e = __expf(scsh[ql * SCST + k] - mx);     // masked -> exp underflows to 0 exactly
        scsh[ql * SCST + k] = e;
        ssum += e;
    }
    #pragma unroll
    for (int off = 8; off > 0; off >>= 1)
        ssum += __shfl_xor_sync(0xffffffffu, ssum, off, 16);

    float inv = (mx == -FLT_MAX) ? 0.f : __frcp_rn(ssum);  // fully-masked row -> all-zero weights

    float* wrow = wrow_base + (size_t)ql * TKn;
    #pragma unroll 4
    for (int i = 0; i < TKn / 16; i++) {
        int k = kl0 + 16 * i;
        float w = scsh[ql * SCST + k] * inv;
        scsh[ql * SCST + k] = w;
        if (write_w) wrow[k] = w;
    }

    // ================= Phase B: out = W @ V =================
    const int d2 = t & 31;    // d pair index (d = 2*d2)
    const int qg = t >> 5;    // 0..7 : owns query rows qg and qg+8
    float2 a0 = make_float2(0.f, 0.f), a1 = make_float2(0.f, 0.f);

    for (int kt = 0; kt < TKn / KTILE; kt++) {
        __syncthreads();   // also covers weight-normalize completion on first iter
        const float2* Vg = (const float2*)(V + ((size_t)bh * TKn + kt * KTILE) * DKn);
        #pragma unroll
        for (int i = 0; i < 16; i++) {
            int idx = t + i * NTHR;
            int r = idx >> 5, c = idx & 31;
            float2 v = Vg[(size_t)r * 32 + c];
            *(float2*)&kvsh[r * KST + 2 * c] = v;
        }
        __syncthreads();

        const int kb = kt * KTILE;
        #pragma unroll 4
        for (int kl = 0; kl < KTILE; kl++) {
            float2 v2 = *(float2*)&kvsh[kl * KST + 2 * d2];
            float w0 = scsh[qg * SCST + kb + kl];
            float w1 = scsh[(qg + 8) * SCST + kb + kl];
            a0 = ffma2(make_float2(w0, w0), v2, a0);
            a1 = ffma2(make_float2(w1, w1), v2, a1);
        }
    }

    *(float2*)&orow_base[(size_t)qg * DKn + 2 * d2]       = a0;
    *(float2*)&orow_base[(size_t)(qg + 8) * DKn + 2 * d2] = a1;
}

// ---------------------------------------------------------------------------
extern "C" void kernel_launch(void* const* d_in, const int* in_sizes, int n_in,
                              void* d_out, int out_size) {
    const float*         Q  = (const float*)d_in[0];
    const float*         K  = (const float*)d_in[1];
    const float*         V  = (const float*)d_in[2];
    const unsigned char* Mb = (const unsigned char*)d_in[3];
    const int*           HA = (const int*)d_in[4];
    const int*           NH = (const int*)d_in[5];
    float*               O  = (float*)d_out;

    // write weights only if the output buffer actually includes them
    int write_w = (out_size >= (int)((size_t)BHn * TQn * (DKn + TKn))) ? 1 : 0;

    cudaFuncSetAttribute(attn_fp32x2_kernel,
                         cudaFuncAttributeMaxDynamicSharedMemorySize, SMEM_BYTES);

    detect_mask_kernel<<<1, 256>>>((const unsigned int*)Mb);

    dim3 grid(TQn / QT, BHn);
    attn_fp32x2_kernel<<<grid, NTHR, SMEM_BYTES>>>(Q, K, V, Mb, HA, NH, O, write_w);
}

// round 2
// speedup vs baseline: 1.0024x; 1.0024x over previous
#include <cuda_runtime.h>
#include <cfloat>

#define BHn   64
#define TQn   1024
#define TKn   1024
#define DKn   64
#define QT    16      // queries per block
#define KTILE 128     // key tile rows staged in smem
#define NTHR  256
#define KST   66      // padded row stride (floats) for K/V/Q tiles  (66 mod 32 = 2 -> conflict-free)
#define SCST  1040    // padded row stride (floats) for score tile   (1040 mod 32 = 16 -> disjoint halves)

#define SMEM_BYTES ((QT*KST + KTILE*KST + QT*SCST) * 4)   // 104576 B

// ---------------------------------------------------------------------------
// mask dtype auto-detect: 1 if mask elements are 1-byte (bool/int8), else 0
// (int32 0/1 data has all bytes at i%4!=0 equal to zero)
// ---------------------------------------------------------------------------
__device__ int g_mask_narrow;

__global__ void detect_mask_kernel(const unsigned int* __restrict__ mw) {
    __shared__ int found;
    if (threadIdx.x == 0) found = 0;
    __syncthreads();
    int local = 0;
    // scan first 64KB (= full bool buffer, or first quarter of an int32 buffer)
    for (int i = threadIdx.x; i < (BHn * TKn) / 4; i += blockDim.x) {
        if (mw[i] & 0xFFFFFF00u) local = 1;
    }
    if (local) atomicOr(&found, 1);
    __syncthreads();
    if (threadIdx.x == 0) g_mask_narrow = found;
}

// packed dual-fp32 FMA (ptxas never emits FFMA2 from C++; PTX f32x2 is required)
__device__ __forceinline__ float2 ffma2(float2 a, float2 b, float2 c) {
    float2 d;
    asm("fma.rn.f32x2 %0, %1, %2, %3;"
        : "=l"(reinterpret_cast<unsigned long long&>(d))
        : "l"(reinterpret_cast<unsigned long long&>(a)),
          "l"(reinterpret_cast<unsigned long long&>(b)),
          "l"(reinterpret_cast<unsigned long long&>(c)));
    return d;
}

// ---------------------------------------------------------------------------
// main attention kernel: one block = (16 queries) x (one bh head)
// ---------------------------------------------------------------------------
extern "C" __global__ void __launch_bounds__(NTHR, 2)
attn_fp32x2_kernel(const float* __restrict__ Q, const float* __restrict__ K,
                   const float* __restrict__ V, const unsigned char* __restrict__ Mb,
                   const int* __restrict__ pHA, const int* __restrict__ pNH,
                   float* __restrict__ Out, int write_w)
{
    extern __shared__ float sm[];
    float* qsh  = sm;                         // [QT][KST]
    float* kvsh = sm + QT * KST;              // [KTILE][KST]
    float* scsh = kvsh + KTILE * KST;         // [QT][SCST]

    const int t  = threadIdx.x;
    const int bh = blockIdx.y;
    const int q0 = blockIdx.x * QT;

    const int nh = pNH[0];                    // low 32 bits: correct for i32 or LE i64
    const int ha = pHA[0];

    float* Wout      = Out + (size_t)BHn * TQn * DKn;
    float* wrow_base = Wout + ((size_t)bh * TQn + q0) * TKn;
    float* orow_base = Out  + ((size_t)bh * TQn + q0) * DKn;

    // ---- head ablation: weights and output are exactly zero ----
    if (nh > 0 && (bh % nh) == ha) {
        float4 z = make_float4(0.f, 0.f, 0.f, 0.f);
        if (write_w) {
            float4* w4 = (float4*)wrow_base;
            #pragma unroll 4
            for (int i = t; i < QT * TKn / 4; i += NTHR) w4[i] = z;
        }
        float4* o4 = (float4*)orow_base;
        for (int i = t; i < QT * DKn / 4; i += NTHR) o4[i] = z;
        return;
    }

    const int shift = g_mask_narrow ? 0 : 2;
    const unsigned char* mrow = Mb + (((size_t)bh * TKn) << shift);

    // ---- load Q tile: 16x64 floats = 512 float2, 2 per thread ----
    {
        const float2* Qg = (const float2*)(Q + ((size_t)bh * TQn + q0) * DKn);
        #pragma unroll
        for (int i = 0; i < 2; i++) {
            int idx = t + i * NTHR;          // 0..511
            int r = idx >> 5, c = idx & 31;  // 32 float2 per row
            float2 v = Qg[(size_t)r * 32 + c];
            *(float2*)&qsh[r * KST + 2 * c] = v;
        }
    }

    const int ql  = t >> 4;   // 0..15 : query row owned in phase A
    const int kl0 = t & 15;   // key lane

    // ================= Phase A: scores = QK^T / 8, masked =================
    for (int kt = 0; kt < TKn / KTILE; kt++) {
        __syncthreads();   // previous tile consumers done
        const float2* Kg = (const float2*)(K + ((size_t)bh * TKn + kt * KTILE) * DKn);
        #pragma unroll
        for (int i = 0; i < 16; i++) {
            int idx = t + i * NTHR;          // 0..4095
            int r = idx >> 5, c = idx & 31;
            float2 v = Kg[(size_t)r * 32 + c];
            *(float2*)&kvsh[r * KST + 2 * c] = v;
        }
        __syncthreads();

        float2 acc[8];
        #pragma unroll
        for (int j = 0; j < 8; j++) acc[j] = make_float2(0.f, 0.f);
        #pragma unroll
        for (int d2 = 0; d2 < 32; d2++) {
            float2 q2 = *(float2*)&qsh[ql * KST + 2 * d2];
            #pragma unroll
            for (int j = 0; j < 8; j++) {
                float2 k2 = *(float2*)&kvsh[(kl0 + 16 * j) * KST + 2 * d2];
                acc[j] = ffma2(q2, k2, acc[j]);
            }
        }
        const int kb = kt * KTILE;
        #pragma unroll
        for (int j = 0; j < 8; j++) {
            int k = kb + kl0 + 16 * j;
            unsigned char m = mrow[(size_t)k << shift];
            float s = (acc[j].x + acc[j].y) * 0.125f;   // 1/sqrt(64)
            scsh[ql * SCST + k] = m ? s : -FLT_MAX;     // == jnp.finfo(f32).min
        }
    }
    __syncthreads();

    // ================= softmax (16 lanes per query row) =================
    float mx = -FLT_MAX;
    #pragma unroll 4
    for (int i = 0; i < TKn / 16; i++)
        mx = fmaxf(mx, scsh[ql * SCST + kl0 + 16 * i]);
    #pragma unroll
    for (int off = 8; off > 0; off >>= 1)
        mx = fmaxf(mx, __shfl_xor_sync(0xffffffffu, mx, off, 16));

    float ssum = 0.f;
    #pragma unroll 4
    for (int i = 0; i < TKn / 16; i++) {
        int k = kl0 + 16 * i;
        float e = __expf(scsh[ql * SCST + k] - mx);     // masked -> exp underflows to 0 exactly
        scsh[ql * SCST + k] = e;
        ssum += e;
    }
    #pragma unroll
    for (int off = 8; off > 0; off >>= 1)
        ssum += __shfl_xor_sync(0xffffffffu, ssum, off, 16);

    float inv = (mx == -FLT_MAX) ? 0.f : __frcp_rn(ssum);  // fully-masked row -> all-zero weights

    float* wrow = wrow_base + (size_t)ql * TKn;
    #pragma unroll 4
    for (int i = 0; i < TKn / 16; i++) {
        int k = kl0 + 16 * i;
        float w = scsh[ql * SCST + k] * inv;
        scsh[ql * SCST + k] = w;
        if (write_w) wrow[k] = w;
    }

    // ================= Phase B: out = W @ V =================
    const int d2 = t & 31;    // d pair index (d = 2*d2)
    const int qg = t >> 5;    // 0..7 : owns query rows qg and qg+8
    float2 a0 = make_float2(0.f, 0.f), a1 = make_float2(0.f, 0.f);

    for (int kt = 0; kt < TKn / KTILE; kt++) {
        __syncthreads();   // also covers weight-normalize completion on first iter
        const float2* Vg = (const float2*)(V + ((size_t)bh * TKn + kt * KTILE) * DKn);
        #pragma unroll
        for (int i = 0; i < 16; i++) {
            int idx = t + i * NTHR;
            int r = idx >> 5, c = idx & 31;
            float2 v = Vg[(size_t)r * 32 + c];
            *(float2*)&kvsh[r * KST + 2 * c] = v;
        }
        __syncthreads();

        const int kb = kt * KTILE;
        #pragma unroll 4
        for (int kl = 0; kl < KTILE; kl++) {
            float2 v2 = *(float2*)&kvsh[kl * KST + 2 * d2];
            float w0 = scsh[qg * SCST + kb + kl];
            float w1 = scsh[(qg + 8) * SCST + kb + kl];
            a0 = ffma2(make_float2(w0, w0), v2, a0);
            a1 = ffma2(make_float2(w1, w1), v2, a1);
        }
    }

    *(float2*)&orow_base[(size_t)qg * DKn + 2 * d2]       = a0;
    *(float2*)&orow_base[(size_t)(qg + 8) * DKn + 2 * d2] = a1;
}

// ---------------------------------------------------------------------------
extern "C" void kernel_launch(void* const* d_in, const int* in_sizes, int n_in,
                              void* d_out, int out_size) {
    const float*         Q  = (const float*)d_in[0];
    const float*         K  = (const float*)d_in[1];
    const float*         V  = (const float*)d_in[2];
    const unsigned char* Mb = (const unsigned char*)d_in[3];
    const int*           HA = (const int*)d_in[4];
    const int*           NH = (const int*)d_in[5];
    float*               O  = (float*)d_out;

    // write weights only if the output buffer actually includes them
    int write_w = (out_size >= (int)((size_t)BHn * TQn * (DKn + TKn))) ? 1 : 0;

    cudaFuncSetAttribute(attn_fp32x2_kernel,
                         cudaFuncAttributeMaxDynamicSharedMemorySize, SMEM_BYTES);

    detect_mask_kernel<<<1, 256>>>((const unsigned int*)Mb);

    dim3 grid(TQn / QT, BHn);
    attn_fp32x2_kernel<<<grid, NTHR, SMEM_BYTES>>>(Q, K, V, Mb, HA, NH, O, write_w);
}

// round 3
// speedup vs baseline: 1.1269x; 1.1242x over previous
#include <cuda_runtime.h>
#include <cfloat>

#define BHn   64
#define TQn   1024
#define TKn   1024
#define DKn   64
#define QT    16      // queries per block
#define KTILE 128     // key/value tile rows staged in smem
#define NTHR  256
#define KST   68      // K/V/Q tile row stride (floats): 68%32=4 -> 8-row LDS.128 conflict-free
#define SCST  1032    // score row stride (floats): 1032%32=8 -> epilogue stores conflict-free

#define SMEM_FLOATS (QT*KST + KTILE*KST + QT*SCST)
#define SMEM_BYTES  (SMEM_FLOATS * 4)      // 105216 B -> 2 blocks/SM

// ---------------------------------------------------------------------------
// mask dtype auto-detect: 1 if mask elements are 1-byte (bool/int8), else 0
// ---------------------------------------------------------------------------
__device__ int g_mask_narrow;

__global__ void detect_mask_kernel(const unsigned int* __restrict__ mw) {
    __shared__ int found;
    if (threadIdx.x == 0) found = 0;
    __syncthreads();
    int local = 0;
    for (int i = threadIdx.x; i < (BHn * TKn) / 4; i += blockDim.x) {
        if (mw[i] & 0xFFFFFF00u) local = 1;
    }
    if (local) atomicOr(&found, 1);
    __syncthreads();
    if (threadIdx.x == 0) g_mask_narrow = found;
}

// packed dual-fp32 FMA (ptxas never emits FFMA2 from C++; PTX f32x2 required)
__device__ __forceinline__ float2 ffma2(float2 a, float2 b, float2 c) {
    float2 d;
    asm("fma.rn.f32x2 %0, %1, %2, %3;"
        : "=l"(reinterpret_cast<unsigned long long&>(d))
        : "l"(reinterpret_cast<unsigned long long&>(a)),
          "l"(reinterpret_cast<unsigned long long&>(b)),
          "l"(reinterpret_cast<unsigned long long&>(c)));
    return d;
}

// ---------------------------------------------------------------------------
// one block = (16 queries) x (one bh head)
// ---------------------------------------------------------------------------
extern "C" __global__ void __launch_bounds__(NTHR, 2)
attn_fp32x2_kernel(const float* __restrict__ Q, const float* __restrict__ K,
                   const float* __restrict__ V, const unsigned char* __restrict__ Mb,
                   const int* __restrict__ pHA, const int* __restrict__ pNH,
                   float* __restrict__ Out, int write_w)
{
    extern __shared__ float sm[];
    float* qsh  = sm;                         // [QT][KST]
    float* kvsh = sm + QT * KST;              // [KTILE][KST]
    float* scsh = kvsh + KTILE * KST;         // [QT][SCST]

    const int t  = threadIdx.x;
    const int w  = t >> 5;                    // warp 0..7
    const int l  = t & 31;
    const int bh = blockIdx.y;
    const int q0 = blockIdx.x * QT;

    const int nh = pNH[0];
    const int ha = pHA[0];

    float* Wout      = Out + (size_t)BHn * TQn * DKn;
    float* wrow_base = Wout + ((size_t)bh * TQn + q0) * TKn;
    float* orow_base = Out  + ((size_t)bh * TQn + q0) * DKn;

    // ---- head ablation: weights and output are exactly zero ----
    if (nh > 0 && (bh % nh) == ha) {
        float4 z = make_float4(0.f, 0.f, 0.f, 0.f);
        if (write_w) {
            float4* w4 = (float4*)wrow_base;
            #pragma unroll 4
            for (int i = t; i < QT * TKn / 4; i += NTHR) w4[i] = z;
        }
        float4* o4 = (float4*)orow_base;
        for (int i = t; i < QT * DKn / 4; i += NTHR) o4[i] = z;
        return;
    }

    const int shift = g_mask_narrow ? 0 : 2;
    const unsigned char* mrow = Mb + (((size_t)bh * TKn) << shift);

    // ---- stage Q tile: 16x64 floats = 256 float4, 1 per thread ----
    {
        const float4* Qg = (const float4*)(Q + ((size_t)bh * TQn + q0) * DKn);
        int r = t >> 4, c4 = t & 15;          // 16 float4 per row
        *(float4*)&qsh[r * KST + 4 * c4] = Qg[t];
    }

    // ================= Phase A: scores = QK^T / 8, masked =================
    // warp w owns k-rows [16w, 16w+16); lane: qg = l>>3 (4 q rows, stride 4),
    // kg = l&7 (2 k rows: kg, kg+8). Register tile 4q x 2k.
    const int qg = l >> 3;
    const int kg = l & 7;

    for (int kt = 0; kt < TKn / KTILE; kt++) {
        __syncthreads();                       // prior tile consumers done
        const float4* Kg = (const float4*)(K + ((size_t)bh * TKn + kt * KTILE) * DKn);
        #pragma unroll
        for (int i = 0; i < 8; i++) {
            int idx = t + i * NTHR;            // 0..2047
            int r = idx >> 4, c4 = idx & 15;
            *(float4*)&kvsh[r * KST + 4 * c4] = Kg[idx];
        }
        __syncthreads();

        float2 acc[4][2];
        #pragma unroll
        for (int qi = 0; qi < 4; qi++) {
            acc[qi][0] = make_float2(0.f, 0.f);
            acc[qi][1] = make_float2(0.f, 0.f);
        }

        const float* krow0 = &kvsh[(16 * w + kg) * KST];
        const float* krow1 = &kvsh[(16 * w + kg + 8) * KST];

        #pragma unroll 4
        for (int d4 = 0; d4 < 16; d4++) {
            float4 k0 = *(const float4*)&krow0[4 * d4];
            float4 k1 = *(const float4*)&krow1[4 * d4];
            #pragma unroll
            for (int qi = 0; qi < 4; qi++) {
                float4 qv = *(const float4*)&qsh[(qg + 4 * qi) * KST + 4 * d4];
                acc[qi][0] = ffma2(make_float2(qv.x, qv.y), make_float2(k0.x, k0.y), acc[qi][0]);
                acc[qi][0] = ffma2(make_float2(qv.z, qv.w), make_float2(k0.z, k0.w), acc[qi][0]);
                acc[qi][1] = ffma2(make_float2(qv.x, qv.y), make_float2(k1.x, k1.y), acc[qi][1]);
                acc[qi][1] = ffma2(make_float2(qv.z, qv.w), make_float2(k1.z, k1.w), acc[qi][1]);
            }
        }

        const int kb = kt * KTILE + 16 * w;
        #pragma unroll
        for (int qi = 0; qi < 4; qi++) {
            #pragma unroll
            for (int kj = 0; kj < 2; kj++) {
                int k = kb + kg + 8 * kj;
                unsigned char m = mrow[(size_t)k << shift];
                float s = (acc[qi][kj].x + acc[qi][kj].y) * 0.125f;   // 1/sqrt(64)
                scsh[(qg + 4 * qi) * SCST + k] = m ? s : -FLT_MAX;
            }
        }
    }
    __syncthreads();

    // ================= softmax (16 lanes per query row) =================
    {
        const int ql  = t >> 4;
        const int kl0 = t & 15;

        float mx = -FLT_MAX;
        #pragma unroll 4
        for (int i = 0; i < TKn / 16; i++)
            mx = fmaxf(mx, scsh[ql * SCST + kl0 + 16 * i]);
        #pragma unroll
        for (int off = 8; off > 0; off >>= 1)
            mx = fmaxf(mx, __shfl_xor_sync(0xffffffffu, mx, off, 16));

        float ssum = 0.f;
        #pragma unroll 4
        for (int i = 0; i < TKn / 16; i++) {
            int k = kl0 + 16 * i;
            float e = __expf(scsh[ql * SCST + k] - mx);   // masked -> exact 0
            scsh[ql * SCST + k] = e;
            ssum += e;
        }
        #pragma unroll
        for (int off = 8; off > 0; off >>= 1)
            ssum += __shfl_xor_sync(0xffffffffu, ssum, off, 16);

        float inv = (mx == -FLT_MAX) ? 0.f : __frcp_rn(ssum);  // fully-masked row

        #pragma unroll 4
        for (int i = 0; i < TKn / 16; i++) {
            int k = kl0 + 16 * i;
            scsh[ql * SCST + k] *= inv;
        }
    }
    __syncthreads();

    // ---- coalesced weights store: 16 float4 per thread ----
    if (write_w) {
        float4* w4 = (float4*)wrow_base;
        #pragma unroll
        for (int i = 0; i < 16; i++) {
            int j  = t + i * NTHR;             // 0..4095 float4 index
            int r  = j >> 8;                   // q row
            int c4 = j & 255;                  // float4 column
            w4[r * 256 + c4] = *(const float4*)&scsh[r * SCST + 4 * c4];
        }
    }

    // ================= Phase B: out = W @ V =================
    // warp w owns d-columns [8w, 8w+8); lane: q = l&15, dh = l>>4 -> float4 of d.
    const int qB  = l & 15;
    const int d4i = 2 * w + (l >> 4);          // float4 column index in V tile

    float2 a01 = make_float2(0.f, 0.f);
    float2 a23 = make_float2(0.f, 0.f);

    for (int kt = 0; kt < TKn / KTILE; kt++) {
        __syncthreads();                       // covers normalize/copy on first iter
        const float4* Vg = (const float4*)(V + ((size_t)bh * TKn + kt * KTILE) * DKn);
        #pragma unroll
        for (int i = 0; i < 8; i++) {
            int idx = t + i * NTHR;
            int r = idx >> 4, c4 = idx & 15;
            *(float4*)&kvsh[r * KST + 4 * c4] = Vg[idx];
        }
        __syncthreads();

        const float* wr = &scsh[qB * SCST + kt * KTILE];
        #pragma unroll 4
        for (int g = 0; g < KTILE / 4; g++) {
            float4 w4 = *(const float4*)&wr[4 * g];
            float4 v0 = *(const float4*)&kvsh[(4 * g + 0) * KST + 4 * d4i];
            float4 v1 = *(const float4*)&kvsh[(4 * g + 1) * KST + 4 * d4i];
            float4 v2 = *(const float4*)&kvsh[(4 * g + 2) * KST + 4 * d4i];
            float4 v3 = *(const float4*)&kvsh[(4 * g + 3) * KST + 4 * d4i];
            a01 = ffma2(make_float2(w4.x, w4.x), make_float2(v0.x, v0.y), a01);
            a23 = ffma2(make_float2(w4.x, w4.x), make_float2(v0.z, v0.w), a23);
            a01 = ffma2(make_float2(w4.y, w4.y), make_float2(v1.x, v1.y), a01);
            a23 = ffma2(make_float2(w4.y, w4.y), make_float2(v1.z, v1.w), a23);
            a01 = ffma2(make_float2(w4.z, w4.z), make_float2(v2.x, v2.y), a01);
            a23 = ffma2(make_float2(w4.z, w4.z), make_float2(v2.z, v2.w), a23);
            a01 = ffma2(make_float2(w4.w, w4.w), make_float2(v3.x, v3.y), a01);
            a23 = ffma2(make_float2(w4.w, w4.w), make_float2(v3.z, v3.w), a23);
        }
    }

    float4 res = make_float4(a01.x, a01.y, a23.x, a23.y);
    *(float4*)&orow_base[(size_t)qB * DKn + 4 * d4i] = res;
}

// ---------------------------------------------------------------------------
extern "C" void kernel_launch(void* const* d_in, const int* in_sizes, int n_in,
                              void* d_out, int out_size) {
    const float*         Q  = (const float*)d_in[0];
    const float*         K  = (const float*)d_in[1];
    const float*         V  = (const float*)d_in[2];
    const unsigned char* Mb = (const unsigned char*)d_in[3];
    const int*           HA = (const int*)d_in[4];
    const int*           NH = (const int*)d_in[5];
    float*               O  = (float*)d_out;

    int write_w = (out_size >= (int)((size_t)BHn * TQn * (DKn + TKn))) ? 1 : 0;

    cudaFuncSetAttribute(attn_fp32x2_kernel,
                         cudaFuncAttributeMaxDynamicSharedMemorySize, SMEM_BYTES);

    detect_mask_kernel<<<1, 256>>>((const unsigned int*)Mb);

    dim3 grid(TQn / QT, BHn);
    attn_fp32x2_kernel<<<grid, NTHR, SMEM_BYTES>>>(Q, K, V, Mb, HA, NH, O, write_w);
}

// round 4
// speedup vs baseline: 1.1270x; 1.0001x over previous
#include <cuda_runtime.h>
#include <cfloat>

#define BHn   64
#define TQn   1024
#define TKn   1024
#define DKn   64
#define QT    16      // queries per block
#define KTILE 128     // key/value tile rows staged in smem
#define NTHR  256
#define KST   68      // K/V/Q tile row stride (floats): 68%32=4 -> 8-row LDS.128 conflict-free
#define SCST  1032    // score row stride (floats): 1032%32=8 -> epilogue stores conflict-free

#define SMEM_FLOATS (QT*KST + KTILE*KST + QT*SCST)
#define SMEM_BYTES  (SMEM_FLOATS * 4)      // 105216 B -> 2 blocks/SM

// ---------------------------------------------------------------------------
// mask dtype auto-detect: 1 if mask elements are 1-byte (bool/int8), else 0
// ---------------------------------------------------------------------------
__device__ int g_mask_narrow;

__global__ void detect_mask_kernel(const unsigned int* __restrict__ mw) {
    __shared__ int found;
    if (threadIdx.x == 0) found = 0;
    __syncthreads();
    int local = 0;
    for (int i = threadIdx.x; i < (BHn * TKn) / 4; i += blockDim.x) {
        if (mw[i] & 0xFFFFFF00u) local = 1;
    }
    if (local) atomicOr(&found, 1);
    __syncthreads();
    if (threadIdx.x == 0) g_mask_narrow = found;
}

// packed dual-fp32 FMA (ptxas never emits FFMA2 from C++; PTX f32x2 required)
__device__ __forceinline__ float2 ffma2(float2 a, float2 b, float2 c) {
    float2 d;
    asm("fma.rn.f32x2 %0, %1, %2, %3;"
        : "=l"(reinterpret_cast<unsigned long long&>(d))
        : "l"(reinterpret_cast<unsigned long long&>(a)),
          "l"(reinterpret_cast<unsigned long long&>(b)),
          "l"(reinterpret_cast<unsigned long long&>(c)));
    return d;
}

// ---------------------------------------------------------------------------
// one block = (16 queries) x (one bh head)
// ---------------------------------------------------------------------------
extern "C" __global__ void __launch_bounds__(NTHR, 2)
attn_fp32x2_kernel(const float* __restrict__ Q, const float* __restrict__ K,
                   const float* __restrict__ V, const unsigned char* __restrict__ Mb,
                   const int* __restrict__ pHA, const int* __restrict__ pNH,
                   float* __restrict__ Out, int write_w)
{
    extern __shared__ float sm[];
    float* qsh  = sm;                         // [QT][KST]
    float* kvsh = sm + QT * KST;              // [KTILE][KST]
    float* scsh = kvsh + KTILE * KST;         // [QT][SCST]

    const int t  = threadIdx.x;
    const int w  = t >> 5;                    // warp 0..7
    const int l  = t & 31;
    const int bh = blockIdx.y;
    const int q0 = blockIdx.x * QT;

    const int nh = pNH[0];
    const int ha = pHA[0];

    float* Wout      = Out + (size_t)BHn * TQn * DKn;
    float* wrow_base = Wout + ((size_t)bh * TQn + q0) * TKn;
    float* orow_base = Out  + ((size_t)bh * TQn + q0) * DKn;

    // ---- head ablation: weights and output are exactly zero ----
    if (nh > 0 && (bh % nh) == ha) {
        float4 z = make_float4(0.f, 0.f, 0.f, 0.f);
        if (write_w) {
            float4* w4 = (float4*)wrow_base;
            #pragma unroll 4
            for (int i = t; i < QT * TKn / 4; i += NTHR) w4[i] = z;
        }
        float4* o4 = (float4*)orow_base;
        for (int i = t; i < QT * DKn / 4; i += NTHR) o4[i] = z;
        return;
    }

    const int shift = g_mask_narrow ? 0 : 2;
    const unsigned char* mrow = Mb + (((size_t)bh * TKn) << shift);

    // ---- stage Q tile: 16x64 floats = 256 float4, 1 per thread ----
    {
        const float4* Qg = (const float4*)(Q + ((size_t)bh * TQn + q0) * DKn);
        int r = t >> 4, c4 = t & 15;          // 16 float4 per row
        *(float4*)&qsh[r * KST + 4 * c4] = Qg[t];
    }

    // ================= Phase A: scores = QK^T / 8, masked =================
    // warp w owns k-rows [16w, 16w+16); lane: qg = l>>3 (4 q rows, stride 4),
    // kg = l&7 (2 k rows: kg, kg+8). Register tile 4q x 2k.
    const int qg = l >> 3;
    const int kg = l & 7;

    for (int kt = 0; kt < TKn / KTILE; kt++) {
        __syncthreads();                       // prior tile consumers done
        const float4* Kg = (const float4*)(K + ((size_t)bh * TKn + kt * KTILE) * DKn);
        #pragma unroll
        for (int i = 0; i < 8; i++) {
            int idx = t + i * NTHR;            // 0..2047
            int r = idx >> 4, c4 = idx & 15;
            *(float4*)&kvsh[r * KST + 4 * c4] = Kg[idx];
        }
        __syncthreads();

        float2 acc[4][2];
        #pragma unroll
        for (int qi = 0; qi < 4; qi++) {
            acc[qi][0] = make_float2(0.f, 0.f);
            acc[qi][1] = make_float2(0.f, 0.f);
        }

        const float* krow0 = &kvsh[(16 * w + kg) * KST];
        const float* krow1 = &kvsh[(16 * w + kg + 8) * KST];

        #pragma unroll 4
        for (int d4 = 0; d4 < 16; d4++) {
            float4 k0 = *(const float4*)&krow0[4 * d4];
            float4 k1 = *(const float4*)&krow1[4 * d4];
            #pragma unroll
            for (int qi = 0; qi < 4; qi++) {
                float4 qv = *(const float4*)&qsh[(qg + 4 * qi) * KST + 4 * d4];
                acc[qi][0] = ffma2(make_float2(qv.x, qv.y), make_float2(k0.x, k0.y), acc[qi][0]);
                acc[qi][0] = ffma2(make_float2(qv.z, qv.w), make_float2(k0.z, k0.w), acc[qi][0]);
                acc[qi][1] = ffma2(make_float2(qv.x, qv.y), make_float2(k1.x, k1.y), acc[qi][1]);
                acc[qi][1] = ffma2(make_float2(qv.z, qv.w), make_float2(k1.z, k1.w), acc[qi][1]);
            }
        }

        const int kb = kt * KTILE + 16 * w;
        #pragma unroll
        for (int qi = 0; qi < 4; qi++) {
            #pragma unroll
            for (int kj = 0; kj < 2; kj++) {
                int k = kb + kg + 8 * kj;
                unsigned char m = mrow[(size_t)k << shift];
                float s = (acc[qi][kj].x + acc[qi][kj].y) * 0.125f;   // 1/sqrt(64)
                scsh[(qg + 4 * qi) * SCST + k] = m ? s : -FLT_MAX;
            }
        }
    }
    __syncthreads();

    // ================= softmax (16 lanes per query row) =================
    {
        const int ql  = t >> 4;
        const int kl0 = t & 15;

        float mx = -FLT_MAX;
        #pragma unroll 4
        for (int i = 0; i < TKn / 16; i++)
            mx = fmaxf(mx, scsh[ql * SCST + kl0 + 16 * i]);
        #pragma unroll
        for (int off = 8; off > 0; off >>= 1)
            mx = fmaxf(mx, __shfl_xor_sync(0xffffffffu, mx, off, 16));

        float ssum = 0.f;
        #pragma unroll 4
        for (int i = 0; i < TKn / 16; i++) {
            int k = kl0 + 16 * i;
            float e = __expf(scsh[ql * SCST + k] - mx);   // masked -> exact 0
            scsh[ql * SCST + k] = e;
            ssum += e;
        }
        #pragma unroll
        for (int off = 8; off > 0; off >>= 1)
            ssum += __shfl_xor_sync(0xffffffffu, ssum, off, 16);

        float inv = (mx == -FLT_MAX) ? 0.f : __frcp_rn(ssum);  // fully-masked row

        #pragma unroll 4
        for (int i = 0; i < TKn / 16; i++) {
            int k = kl0 + 16 * i;
            scsh[ql * SCST + k] *= inv;
        }
    }
    __syncthreads();

    // ---- coalesced weights store: 16 float4 per thread ----
    if (write_w) {
        float4* w4 = (float4*)wrow_base;
        #pragma unroll
        for (int i = 0; i < 16; i++) {
            int j  = t + i * NTHR;             // 0..4095 float4 index
            int r  = j >> 8;                   // q row
            int c4 = j & 255;                  // float4 column
            w4[r * 256 + c4] = *(const float4*)&scsh[r * SCST + 4 * c4];
        }
    }

    // ================= Phase B: out = W @ V =================
    // warp w owns d-columns [8w, 8w+8); lane: q = l&15, dh = l>>4 -> float4 of d.
    const int qB  = l & 15;
    const int d4i = 2 * w + (l >> 4);          // float4 column index in V tile

    float2 a01 = make_float2(0.f, 0.f);
    float2 a23 = make_float2(0.f, 0.f);

    for (int kt = 0; kt < TKn / KTILE; kt++) {
        __syncthreads();                       // covers normalize/copy on first iter
        const float4* Vg = (const float4*)(V + ((size_t)bh * TKn + kt * KTILE) * DKn);
        #pragma unroll
        for (int i = 0; i < 8; i++) {
            int idx = t + i * NTHR;
            int r = idx >> 4, c4 = idx & 15;
            *(float4*)&kvsh[r * KST + 4 * c4] = Vg[idx];
        }
        __syncthreads();

        const float* wr = &scsh[qB * SCST + kt * KTILE];
        #pragma unroll 4
        for (int g = 0; g < KTILE / 4; g++) {
            float4 w4 = *(const float4*)&wr[4 * g];
            float4 v0 = *(const float4*)&kvsh[(4 * g + 0) * KST + 4 * d4i];
            float4 v1 = *(const float4*)&kvsh[(4 * g + 1) * KST + 4 * d4i];
            float4 v2 = *(const float4*)&kvsh[(4 * g + 2) * KST + 4 * d4i];
            float4 v3 = *(const float4*)&kvsh[(4 * g + 3) * KST + 4 * d4i];
            a01 = ffma2(make_float2(w4.x, w4.x), make_float2(v0.x, v0.y), a01);
            a23 = ffma2(make_float2(w4.x, w4.x), make_float2(v0.z, v0.w), a23);
            a01 = ffma2(make_float2(w4.y, w4.y), make_float2(v1.x, v1.y), a01);
            a23 = ffma2(make_float2(w4.y, w4.y), make_float2(v1.z, v1.w), a23);
            a01 = ffma2(make_float2(w4.z, w4.z), make_float2(v2.x, v2.y), a01);
            a23 = ffma2(make_float2(w4.z, w4.z), make_float2(v2.z, v2.w), a23);
            a01 = ffma2(make_float2(w4.w, w4.w), make_float2(v3.x, v3.y), a01);
            a23 = ffma2(make_float2(w4.w, w4.w), make_float2(v3.z, v3.w), a23);
        }
    }

    float4 res = make_float4(a01.x, a01.y, a23.x, a23.y);
    *(float4*)&orow_base[(size_t)qB * DKn + 4 * d4i] = res;
}

// ---------------------------------------------------------------------------
extern "C" void kernel_launch(void* const* d_in, const int* in_sizes, int n_in,
                              void* d_out, int out_size) {
    const float*         Q  = (const float*)d_in[0];
    const float*         K  = (const float*)d_in[1];
    const float*         V  = (const float*)d_in[2];
    const unsigned char* Mb = (const unsigned char*)d_in[3];
    const int*           HA = (const int*)d_in[4];
    const int*           NH = (const int*)d_in[5];
    float*               O  = (float*)d_out;

    int write_w = (out_size >= (int)((size_t)BHn * TQn * (DKn + TKn))) ? 1 : 0;

    cudaFuncSetAttribute(attn_fp32x2_kernel,
                         cudaFuncAttributeMaxDynamicSharedMemorySize, SMEM_BYTES);

    detect_mask_kernel<<<1, 256>>>((const unsigned int*)Mb);

    dim3 grid(TQn / QT, BHn);
    attn_fp32x2_kernel<<<grid, NTHR, SMEM_BYTES>>>(Q, K, V, Mb, HA, NH, O, write_w);
}

// round 5
// speedup vs baseline: 1.4624x; 1.2976x over previous
#include <cuda_runtime.h>
#include <cfloat>

#define BHn   64
#define TQn   1024
#define TKn   1024
#define DKn   64
#define QT    32      // queries per block
#define KTILE 128     // key/value tile rows staged in smem
#define NTHR  512     // 16 warps
#define KST   68      // K/V/Q tile row stride: 68%32=4 -> conflict-free f4 row loads
#define SCST  1028    // score row stride: 1028%32=4 -> Phase-B weight f4 loads conflict-free

#define SMEM_FLOATS (QT*KST + KTILE*KST + QT*SCST + 32)
#define SMEM_BYTES  (SMEM_FLOATS * 4)      // 175360 B -> 1 block/SM

// ---------------------------------------------------------------------------
__device__ int g_mask_narrow;

__global__ void detect_mask_kernel(const unsigned int* __restrict__ mw) {
    __shared__ int found;
    if (threadIdx.x == 0) found = 0;
    __syncthreads();
    int local = 0;
    for (int i = threadIdx.x; i < (BHn * TKn) / 4; i += blockDim.x) {
        if (mw[i] & 0xFFFFFF00u) local = 1;
    }
    if (local) atomicOr(&found, 1);
    __syncthreads();
    if (threadIdx.x == 0) g_mask_narrow = found;
}

// packed dual-fp32 FMA (ptxas never emits FFMA2 from C++)
__device__ __forceinline__ float2 ffma2(float2 a, float2 b, float2 c) {
    float2 d;
    asm("fma.rn.f32x2 %0, %1, %2, %3;"
        : "=l"(reinterpret_cast<unsigned long long&>(d))
        : "l"(reinterpret_cast<unsigned long long&>(a)),
          "l"(reinterpret_cast<unsigned long long&>(b)),
          "l"(reinterpret_cast<unsigned long long&>(c)));
    return d;
}

// tile = 128 rows x 16 float4; 4 float4 per thread
__device__ __forceinline__ void ldg_tile(float4 pf[4], const float4* __restrict__ g, int t) {
    #pragma unroll
    for (int i = 0; i < 4; i++) pf[i] = g[t + i * NTHR];
}
__device__ __forceinline__ void sts_tile(const float4 pf[4], float* sh, int t) {
    #pragma unroll
    for (int i = 0; i < 4; i++) {
        int idx = t + i * NTHR;
        int r = idx >> 4, c4 = idx & 15;
        *(float4*)&sh[r * KST + 4 * c4] = pf[i];
    }
}

// ---------------------------------------------------------------------------
// one block = 32 queries x one bh head
// ---------------------------------------------------------------------------
extern "C" __global__ void __launch_bounds__(NTHR, 1)
attn_fp32x2_kernel(const float* __restrict__ Q, const float* __restrict__ K,
                   const float* __restrict__ V, const unsigned char* __restrict__ Mb,
                   const int* __restrict__ pHA, const int* __restrict__ pNH,
                   float* __restrict__ Out, int write_w)
{
    extern __shared__ float sm[];
    float* qsh   = sm;                         // [QT][KST]
    float* kvsh  = sm + QT * KST;              // [KTILE][KST]  (also reduction buffer)
    float* scsh  = kvsh + KTILE * KST;         // [QT][SCST]    (scores -> unnormalized e)
    float* invsh = scsh + QT * SCST;           // [32]

    const int t  = threadIdx.x;
    const int w  = t >> 5;                     // warp 0..15
    const int l  = t & 31;
    const int bh = blockIdx.y;
    const int q0 = blockIdx.x * QT;

    const int nh = pNH[0];
    const int ha = pHA[0];

    float* Wout      = Out + (size_t)BHn * TQn * DKn;
    float* wrow_base = Wout + ((size_t)bh * TQn + q0) * TKn;
    float* orow_base = Out  + ((size_t)bh * TQn + q0) * DKn;

    // ---- head ablation: weights and output exactly zero ----
    if (nh > 0 && (bh % nh) == ha) {
        float4 z = make_float4(0.f, 0.f, 0.f, 0.f);
        if (write_w) {
            float4* w4 = (float4*)wrow_base;
            #pragma unroll 4
            for (int i = t; i < QT * TKn / 4; i += NTHR) w4[i] = z;
        }
        ((float4*)orow_base)[t] = z;           // 512 float4 = 32x64 floats
        return;
    }

    const int shift = g_mask_narrow ? 0 : 2;
    const unsigned char* mrow = Mb + (((size_t)bh * TKn) << shift);

    const float4* Kg = (const float4*)(K + ((size_t)bh * TKn) * DKn);
    const float4* Vg = (const float4*)(V + ((size_t)bh * TKn) * DKn);

    // ---- stage Q tile: 32x64 floats = 512 float4, 1 per thread ----
    {
        const float4* Qg = (const float4*)(Q + ((size_t)bh * TQn + q0) * DKn);
        int r = t >> 4, c4 = t & 15;
        *(float4*)&qsh[r * KST + 4 * c4] = Qg[t];
    }

    // prefetch K tile 0 into registers
    float4 pf[4];
    ldg_tile(pf, Kg, t);

    // ================= Phase A: scores = QK^T / 8, masked =================
    // warp: q rows [16*(w>>3), +16), k rows [16*(w&7), +16) of the tile.
    // lane: qg=l>>3 (4 q rows, stride 4), kg=l&7 (2 k rows: kg, kg+8).
    const int qA = 16 * (w >> 3);
    const int kbase16 = 16 * (w & 7);
    const int qg = l >> 3;
    const int kg = l & 7;

    for (int kt = 0; kt < TKn / KTILE; kt++) {
        __syncthreads();                       // prior tile consumers done
        sts_tile(pf, kvsh, t);
        __syncthreads();
        if (kt < 7) ldg_tile(pf, Kg + (size_t)(kt + 1) * KTILE * (DKn / 4), t);
        else        ldg_tile(pf, Vg, t);       // prefetch V tile 0 for Phase B

        float2 acc[4][2];
        #pragma unroll
        for (int qi = 0; qi < 4; qi++) {
            acc[qi][0] = make_float2(0.f, 0.f);
            acc[qi][1] = make_float2(0.f, 0.f);
        }

        const float* krow0 = &kvsh[(kbase16 + kg) * KST];
        const float* krow1 = &kvsh[(kbase16 + kg + 8) * KST];

        #pragma unroll 4
        for (int d4 = 0; d4 < 16; d4++) {
            float4 k0 = *(const float4*)&krow0[4 * d4];
            float4 k1 = *(const float4*)&krow1[4 * d4];
            #pragma unroll
            for (int qi = 0; qi < 4; qi++) {
                float4 qv = *(const float4*)&qsh[(qA + qg + 4 * qi) * KST + 4 * d4];
                acc[qi][0] = ffma2(make_float2(qv.x, qv.y), make_float2(k0.x, k0.y), acc[qi][0]);
                acc[qi][0] = ffma2(make_float2(qv.z, qv.w), make_float2(k0.z, k0.w), acc[qi][0]);
                acc[qi][1] = ffma2(make_float2(qv.x, qv.y), make_float2(k1.x, k1.y), acc[qi][1]);
                acc[qi][1] = ffma2(make_float2(qv.z, qv.w), make_float2(k1.z, k1.w), acc[qi][1]);
            }
        }

        const int kb = kt * KTILE + kbase16;
        #pragma unroll
        for (int qi = 0; qi < 4; qi++) {
            #pragma unroll
            for (int kj = 0; kj < 2; kj++) {
                int k = kb + kg + 8 * kj;
                unsigned char m = mrow[(size_t)k << shift];
                float s = (acc[qi][kj].x + acc[qi][kj].y) * 0.125f;   // 1/sqrt(64)
                scsh[(qA + qg + 4 * qi) * SCST + k] = m ? s : -FLT_MAX;
            }
        }
    }
    __syncthreads();

    // ================= softmax: warp w handles rows 2w, 2w+1 ================
    // scsh ends up holding UNNORMALIZED exp; invsh[r] holds 1/sum (0 if fully masked)
    #pragma unroll
    for (int rr = 0; rr < 2; rr++) {
        int r = 2 * w + rr;
        float* row = &scsh[r * SCST];

        float mx = -FLT_MAX;
        #pragma unroll
        for (int i = 0; i < 8; i++) {
            float4 x = *(const float4*)&row[4 * l + 128 * i];
            mx = fmaxf(mx, fmaxf(fmaxf(x.x, x.y), fmaxf(x.z, x.w)));
        }
        #pragma unroll
        for (int off = 16; off > 0; off >>= 1)
            mx = fmaxf(mx, __shfl_xor_sync(0xffffffffu, mx, off));

        float s = 0.f;
        #pragma unroll
        for (int i = 0; i < 8; i++) {
            float4 x = *(const float4*)&row[4 * l + 128 * i];
            x.x = __expf(x.x - mx);
            x.y = __expf(x.y - mx);
            x.z = __expf(x.z - mx);
            x.w = __expf(x.w - mx);
            *(float4*)&row[4 * l + 128 * i] = x;
            s += (x.x + x.y) + (x.z + x.w);
        }
        #pragma unroll
        for (int off = 16; off > 0; off >>= 1)
            s += __shfl_xor_sync(0xffffffffu, s, off);

        if (l == 0) invsh[r] = (mx == -FLT_MAX) ? 0.f : __frcp_rn(s);
    }
    __syncthreads();

    // ---- coalesced weights store (normalized on the fly) ----
    if (write_w) {
        float4* w4 = (float4*)wrow_base;
        #pragma unroll
        for (int i = 0; i < 16; i++) {
            int j  = t + i * NTHR;             // 0..8191 float4 index
            int r  = j >> 8;                   // q row
            int c4 = j & 255;
            float inv = invsh[r];
            float4 e = *(const float4*)&scsh[r * SCST + 4 * c4];
            e.x *= inv; e.y *= inv; e.z *= inv; e.w *= inv;
            w4[r * 256 + c4] = e;
        }
    }

    // ================= Phase B: out = E @ V (then * inv) =================
    // warp: q rows [16*(w&1),+16), d4 cols [4*((w>>1)&3),+4), k-half kh=w>>3.
    // lane: qp=l>>2 -> q rows qB+qp, qB+qp+8; dg=l&3 -> d4 col.
    const int qB  = 16 * (w & 1);
    const int d4i = 4 * ((w >> 1) & 3) + (l & 3);
    const int kh  = (w >> 3) * 64;             // 0 or 64
    const int qp  = l >> 2;

    float2 a0lo = make_float2(0.f, 0.f), a0hi = make_float2(0.f, 0.f);
    float2 a1lo = make_float2(0.f, 0.f), a1hi = make_float2(0.f, 0.f);

    for (int kt = 0; kt < TKn / KTILE; kt++) {
        __syncthreads();
        sts_tile(pf, kvsh, t);
        __syncthreads();
        if (kt < 7) ldg_tile(pf, Vg + (size_t)(kt + 1) * KTILE * (DKn / 4), t);

        const float* wr0 = &scsh[(qB + qp) * SCST + kt * KTILE + kh];
        const float* wr1 = wr0 + 8 * SCST;
        #pragma unroll 4
        for (int g = 0; g < 16; g++) {
            float4 w0 = *(const float4*)&wr0[4 * g];
            float4 w1 = *(const float4*)&wr1[4 * g];
            float4 v0 = *(const float4*)&kvsh[(kh + 4 * g + 0) * KST + 4 * d4i];
            float4 v1 = *(const float4*)&kvsh[(kh + 4 * g + 1) * KST + 4 * d4i];
            float4 v2 = *(const float4*)&kvsh[(kh + 4 * g + 2) * KST + 4 * d4i];
            float4 v3 = *(const float4*)&kvsh[(kh + 4 * g + 3) * KST + 4 * d4i];

            a0lo = ffma2(make_float2(w0.x, w0.x), make_float2(v0.x, v0.y), a0lo);
            a0hi = ffma2(make_float2(w0.x, w0.x), make_float2(v0.z, v0.w), a0hi);
            a1lo = ffma2(make_float2(w1.x, w1.x), make_float2(v0.x, v0.y), a1lo);
            a1hi = ffma2(make_float2(w1.x, w1.x), make_float2(v0.z, v0.w), a1hi);

            a0lo = ffma2(make_float2(w0.y, w0.y), make_float2(v1.x, v1.y), a0lo);
            a0hi = ffma2(make_float2(w0.y, w0.y), make_float2(v1.z, v1.w), a0hi);
            a1lo = ffma2(make_float2(w1.y, w1.y), make_float2(v1.x, v1.y), a1lo);
            a1hi = ffma2(make_float2(w1.y, w1.y), make_float2(v1.z, v1.w), a1hi);

            a0lo = ffma2(make_float2(w0.z, w0.z), make_float2(v2.x, v2.y), a0lo);
            a0hi = ffma2(make_float2(w0.z, w0.z), make_float2(v2.z, v2.w), a0hi);
            a1lo = ffma2(make_float2(w1.z, w1.z), make_float2(v2.x, v2.y), a1lo);
            a1hi = ffma2(make_float2(w1.z, w1.z), make_float2(v2.z, v2.w), a1hi);

            a0lo = ffma2(make_float2(w0.w, w0.w), make_float2(v3.x, v3.y), a0lo);
            a0hi = ffma2(make_float2(w0.w, w0.w), make_float2(v3.z, v3.w), a0hi);
            a1lo = ffma2(make_float2(w1.w, w1.w), make_float2(v3.x, v3.y), a1lo);
            a1hi = ffma2(make_float2(w1.w, w1.w), make_float2(v3.z, v3.w), a1hi);
        }
    }

    // ---- cross-k-half reduction via smem (reuse kvsh), then scale & store ----
    __syncthreads();                           // kvsh free
    if (w >= 8) {
        float* p = &kvsh[(size_t)((w - 8) * 32 + l) * 8];
        p[0] = a0lo.x; p[1] = a0lo.y; p[2] = a0hi.x; p[3] = a0hi.y;
        p[4] = a1lo.x; p[5] = a1lo.y; p[6] = a1hi.x; p[7] = a1hi.y;
    }
    __syncthreads();
    if (w < 8) {
        const float* p = &kvsh[(size_t)(w * 32 + l) * 8];
        float inv0 = invsh[qB + qp];
        float inv1 = invsh[qB + qp + 8];
        float4 r0 = make_float4((a0lo.x + p[0]) * inv0, (a0lo.y + p[1]) * inv0,
                                (a0hi.x + p[2]) * inv0, (a0hi.y + p[3]) * inv0);
        float4 r1 = make_float4((a1lo.x + p[4]) * inv1, (a1lo.y + p[5]) * inv1,
                                (a1hi.x + p[6]) * inv1, (a1hi.y + p[7]) * inv1);
        *(float4*)&orow_base[(size_t)(qB + qp) * DKn + 4 * d4i]     = r0;
        *(float4*)&orow_base[(size_t)(qB + qp + 8) * DKn + 4 * d4i] = r1;
    }
}

// ---------------------------------------------------------------------------
extern "C" void kernel_launch(void* const* d_in, const int* in_sizes, int n_in,
                              void* d_out, int out_size) {
    const float*         Q  = (const float*)d_in[0];
    const float*         K  = (const float*)d_in[1];
    const float*         V  = (const float*)d_in[2];
    const unsigned char* Mb = (const unsigned char*)d_in[3];
    const int*           HA = (const int*)d_in[4];
    const int*           NH = (const int*)d_in[5];
    float*               O  = (float*)d_out;

    int write_w = (out_size >= (int)((size_t)BHn * TQn * (DKn + TKn))) ? 1 : 0;

    cudaFuncSetAttribute(attn_fp32x2_kernel,
                         cudaFuncAttributeMaxDynamicSharedMemorySize, SMEM_BYTES);

    detect_mask_kernel<<<1, 256>>>((const unsigned int*)Mb);

    dim3 grid(TQn / QT, BHn);
    attn_fp32x2_kernel<<<grid, NTHR, SMEM_BYTES>>>(Q, K, V, Mb, HA, NH, O, write_w);
}

// round 6
// speedup vs baseline: 1.4627x; 1.0002x over previous
#include <cuda_runtime.h>
#include <cfloat>

#define BHn   64
#define TQn   1024
#define TKn   1024
#define DKn   64
#define QT    32      // queries per block
#define KTILE 128     // key/value tile rows staged in smem
#define NTHR  512     // 16 warps
#define KST   68      // K/V/Q tile row stride: 68%32=4 -> conflict-free f4 row loads
#define SCST  1028    // score row stride: 1028%32=4 -> Phase-B weight f4 loads conflict-free

#define SMEM_FLOATS (QT*KST + KTILE*KST + QT*SCST + 32)
#define SMEM_BYTES  (SMEM_FLOATS * 4)      // 175360 B -> 1 block/SM

// ---------------------------------------------------------------------------
__device__ int g_mask_narrow;

__global__ void detect_mask_kernel(const unsigned int* __restrict__ mw) {
    __shared__ int found;
    if (threadIdx.x == 0) found = 0;
    __syncthreads();
    int local = 0;
    for (int i = threadIdx.x; i < (BHn * TKn) / 4; i += blockDim.x) {
        if (mw[i] & 0xFFFFFF00u) local = 1;
    }
    if (local) atomicOr(&found, 1);
    __syncthreads();
    if (threadIdx.x == 0) g_mask_narrow = found;
}

// packed dual-fp32 FMA (ptxas never emits FFMA2 from C++)
__device__ __forceinline__ float2 ffma2(float2 a, float2 b, float2 c) {
    float2 d;
    asm("fma.rn.f32x2 %0, %1, %2, %3;"
        : "=l"(reinterpret_cast<unsigned long long&>(d))
        : "l"(reinterpret_cast<unsigned long long&>(a)),
          "l"(reinterpret_cast<unsigned long long&>(b)),
          "l"(reinterpret_cast<unsigned long long&>(c)));
    return d;
}

// tile = 128 rows x 16 float4; 4 float4 per thread
__device__ __forceinline__ void ldg_tile(float4 pf[4], const float4* __restrict__ g, int t) {
    #pragma unroll
    for (int i = 0; i < 4; i++) pf[i] = g[t + i * NTHR];
}
__device__ __forceinline__ void sts_tile(const float4 pf[4], float* sh, int t) {
    #pragma unroll
    for (int i = 0; i < 4; i++) {
        int idx = t + i * NTHR;
        int r = idx >> 4, c4 = idx & 15;
        *(float4*)&sh[r * KST + 4 * c4] = pf[i];
    }
}

// ---------------------------------------------------------------------------
// one block = 32 queries x one bh head
// ---------------------------------------------------------------------------
extern "C" __global__ void __launch_bounds__(NTHR, 1)
attn_fp32x2_kernel(const float* __restrict__ Q, const float* __restrict__ K,
                   const float* __restrict__ V, const unsigned char* __restrict__ Mb,
                   const int* __restrict__ pHA, const int* __restrict__ pNH,
                   float* __restrict__ Out, int write_w)
{
    extern __shared__ float sm[];
    float* qsh   = sm;                         // [QT][KST]
    float* kvsh  = sm + QT * KST;              // [KTILE][KST]  (also reduction buffer)
    float* scsh  = kvsh + KTILE * KST;         // [QT][SCST]    (scores -> unnormalized e)
    float* invsh = scsh + QT * SCST;           // [32]

    const int t  = threadIdx.x;
    const int w  = t >> 5;                     // warp 0..15
    const int l  = t & 31;
    const int bh = blockIdx.y;
    const int q0 = blockIdx.x * QT;

    const int nh = pNH[0];
    const int ha = pHA[0];

    float* Wout      = Out + (size_t)BHn * TQn * DKn;
    float* wrow_base = Wout + ((size_t)bh * TQn + q0) * TKn;
    float* orow_base = Out  + ((size_t)bh * TQn + q0) * DKn;

    // ---- head ablation: weights and output exactly zero ----
    if (nh > 0 && (bh % nh) == ha) {
        float4 z = make_float4(0.f, 0.f, 0.f, 0.f);
        if (write_w) {
            float4* w4 = (float4*)wrow_base;
            #pragma unroll 4
            for (int i = t; i < QT * TKn / 4; i += NTHR) w4[i] = z;
        }
        ((float4*)orow_base)[t] = z;           // 512 float4 = 32x64 floats
        return;
    }

    const int shift = g_mask_narrow ? 0 : 2;
    const unsigned char* mrow = Mb + (((size_t)bh * TKn) << shift);

    const float4* Kg = (const float4*)(K + ((size_t)bh * TKn) * DKn);
    const float4* Vg = (const float4*)(V + ((size_t)bh * TKn) * DKn);

    // ---- stage Q tile: 32x64 floats = 512 float4, 1 per thread ----
    {
        const float4* Qg = (const float4*)(Q + ((size_t)bh * TQn + q0) * DKn);
        int r = t >> 4, c4 = t & 15;
        *(float4*)&qsh[r * KST + 4 * c4] = Qg[t];
    }

    // prefetch K tile 0 into registers
    float4 pf[4];
    ldg_tile(pf, Kg, t);

    // ================= Phase A: scores = QK^T / 8, masked =================
    // warp: q rows [16*(w>>3), +16), k rows [16*(w&7), +16) of the tile.
    // lane: qg=l>>3 (4 q rows, stride 4), kg=l&7 (2 k rows: kg, kg+8).
    const int qA = 16 * (w >> 3);
    const int kbase16 = 16 * (w & 7);
    const int qg = l >> 3;
    const int kg = l & 7;

    for (int kt = 0; kt < TKn / KTILE; kt++) {
        __syncthreads();                       // prior tile consumers done
        sts_tile(pf, kvsh, t);
        __syncthreads();
        if (kt < 7) ldg_tile(pf, Kg + (size_t)(kt + 1) * KTILE * (DKn / 4), t);
        else        ldg_tile(pf, Vg, t);       // prefetch V tile 0 for Phase B

        float2 acc[4][2];
        #pragma unroll
        for (int qi = 0; qi < 4; qi++) {
            acc[qi][0] = make_float2(0.f, 0.f);
            acc[qi][1] = make_float2(0.f, 0.f);
        }

        const float* krow0 = &kvsh[(kbase16 + kg) * KST];
        const float* krow1 = &kvsh[(kbase16 + kg + 8) * KST];

        #pragma unroll 4
        for (int d4 = 0; d4 < 16; d4++) {
            float4 k0 = *(const float4*)&krow0[4 * d4];
            float4 k1 = *(const float4*)&krow1[4 * d4];
            #pragma unroll
            for (int qi = 0; qi < 4; qi++) {
                float4 qv = *(const float4*)&qsh[(qA + qg + 4 * qi) * KST + 4 * d4];
                acc[qi][0] = ffma2(make_float2(qv.x, qv.y), make_float2(k0.x, k0.y), acc[qi][0]);
                acc[qi][0] = ffma2(make_float2(qv.z, qv.w), make_float2(k0.z, k0.w), acc[qi][0]);
                acc[qi][1] = ffma2(make_float2(qv.x, qv.y), make_float2(k1.x, k1.y), acc[qi][1]);
                acc[qi][1] = ffma2(make_float2(qv.z, qv.w), make_float2(k1.z, k1.w), acc[qi][1]);
            }
        }

        const int kb = kt * KTILE + kbase16;
        #pragma unroll
        for (int qi = 0; qi < 4; qi++) {
            #pragma unroll
            for (int kj = 0; kj < 2; kj++) {
                int k = kb + kg + 8 * kj;
                unsigned char m = mrow[(size_t)k << shift];
                float s = (acc[qi][kj].x + acc[qi][kj].y) * 0.125f;   // 1/sqrt(64)
                scsh[(qA + qg + 4 * qi) * SCST + k] = m ? s : -FLT_MAX;
            }
        }
    }
    __syncthreads();

    // ================= softmax: warp w handles rows 2w, 2w+1 ================
    // scsh ends up holding UNNORMALIZED exp; invsh[r] holds 1/sum (0 if fully masked)
    #pragma unroll
    for (int rr = 0; rr < 2; rr++) {
        int r = 2 * w + rr;
        float* row = &scsh[r * SCST];

        float mx = -FLT_MAX;
        #pragma unroll
        for (int i = 0; i < 8; i++) {
            float4 x = *(const float4*)&row[4 * l + 128 * i];
            mx = fmaxf(mx, fmaxf(fmaxf(x.x, x.y), fmaxf(x.z, x.w)));
        }
        #pragma unroll
        for (int off = 16; off > 0; off >>= 1)
            mx = fmaxf(mx, __shfl_xor_sync(0xffffffffu, mx, off));

        float s = 0.f;
        #pragma unroll
        for (int i = 0; i < 8; i++) {
            float4 x = *(const float4*)&row[4 * l + 128 * i];
            x.x = __expf(x.x - mx);
            x.y = __expf(x.y - mx);
            x.z = __expf(x.z - mx);
            x.w = __expf(x.w - mx);
            *(float4*)&row[4 * l + 128 * i] = x;
            s += (x.x + x.y) + (x.z + x.w);
        }
        #pragma unroll
        for (int off = 16; off > 0; off >>= 1)
            s += __shfl_xor_sync(0xffffffffu, s, off);

        if (l == 0) invsh[r] = (mx == -FLT_MAX) ? 0.f : __frcp_rn(s);
    }
    __syncthreads();

    // ---- coalesced weights store (normalized on the fly) ----
    if (write_w) {
        float4* w4 = (float4*)wrow_base;
        #pragma unroll
        for (int i = 0; i < 16; i++) {
            int j  = t + i * NTHR;             // 0..8191 float4 index
            int r  = j >> 8;                   // q row
            int c4 = j & 255;
            float inv = invsh[r];
            float4 e = *(const float4*)&scsh[r * SCST + 4 * c4];
            e.x *= inv; e.y *= inv; e.z *= inv; e.w *= inv;
            w4[r * 256 + c4] = e;
        }
    }

    // ================= Phase B: out = E @ V (then * inv) =================
    // warp: q rows [16*(w&1),+16), d4 cols [4*((w>>1)&3),+4), k-half kh=w>>3.
    // lane: qp=l>>2 -> q rows qB+qp, qB+qp+8; dg=l&3 -> d4 col.
    const int qB  = 16 * (w & 1);
    const int d4i = 4 * ((w >> 1) & 3) + (l & 3);
    const int kh  = (w >> 3) * 64;             // 0 or 64
    const int qp  = l >> 2;

    float2 a0lo = make_float2(0.f, 0.f), a0hi = make_float2(0.f, 0.f);
    float2 a1lo = make_float2(0.f, 0.f), a1hi = make_float2(0.f, 0.f);

    for (int kt = 0; kt < TKn / KTILE; kt++) {
        __syncthreads();
        sts_tile(pf, kvsh, t);
        __syncthreads();
        if (kt < 7) ldg_tile(pf, Vg + (size_t)(kt + 1) * KTILE * (DKn / 4), t);

        const float* wr0 = &scsh[(qB + qp) * SCST + kt * KTILE + kh];
        const float* wr1 = wr0 + 8 * SCST;
        #pragma unroll 4
        for (int g = 0; g < 16; g++) {
            float4 w0 = *(const float4*)&wr0[4 * g];
            float4 w1 = *(const float4*)&wr1[4 * g];
            float4 v0 = *(const float4*)&kvsh[(kh + 4 * g + 0) * KST + 4 * d4i];
            float4 v1 = *(const float4*)&kvsh[(kh + 4 * g + 1) * KST + 4 * d4i];
            float4 v2 = *(const float4*)&kvsh[(kh + 4 * g + 2) * KST + 4 * d4i];
            float4 v3 = *(const float4*)&kvsh[(kh + 4 * g + 3) * KST + 4 * d4i];

            a0lo = ffma2(make_float2(w0.x, w0.x), make_float2(v0.x, v0.y), a0lo);
            a0hi = ffma2(make_float2(w0.x, w0.x), make_float2(v0.z, v0.w), a0hi);
            a1lo = ffma2(make_float2(w1.x, w1.x), make_float2(v0.x, v0.y), a1lo);
            a1hi = ffma2(make_float2(w1.x, w1.x), make_float2(v0.z, v0.w), a1hi);

            a0lo = ffma2(make_float2(w0.y, w0.y), make_float2(v1.x, v1.y), a0lo);
            a0hi = ffma2(make_float2(w0.y, w0.y), make_float2(v1.z, v1.w), a0hi);
            a1lo = ffma2(make_float2(w1.y, w1.y), make_float2(v1.x, v1.y), a1lo);
            a1hi = ffma2(make_float2(w1.y, w1.y), make_float2(v1.z, v1.w), a1hi);

            a0lo = ffma2(make_float2(w0.z, w0.z), make_float2(v2.x, v2.y), a0lo);
            a0hi = ffma2(make_float2(w0.z, w0.z), make_float2(v2.z, v2.w), a0hi);
            a1lo = ffma2(make_float2(w1.z, w1.z), make_float2(v2.x, v2.y), a1lo);
            a1hi = ffma2(make_float2(w1.z, w1.z), make_float2(v2.z, v2.w), a1hi);

            a0lo = ffma2(make_float2(w0.w, w0.w), make_float2(v3.x, v3.y), a0lo);
            a0hi = ffma2(make_float2(w0.w, w0.w), make_float2(v3.z, v3.w), a0hi);
            a1lo = ffma2(make_float2(w1.w, w1.w), make_float2(v3.x, v3.y), a1lo);
            a1hi = ffma2(make_float2(w1.w, w1.w), make_float2(v3.z, v3.w), a1hi);
        }
    }

    // ---- cross-k-half reduction via smem (reuse kvsh), then scale & store ----
    __syncthreads();                           // kvsh free
    if (w >= 8) {
        float* p = &kvsh[(size_t)((w - 8) * 32 + l) * 8];
        p[0] = a0lo.x; p[1] = a0lo.y; p[2] = a0hi.x; p[3] = a0hi.y;
        p[4] = a1lo.x; p[5] = a1lo.y; p[6] = a1hi.x; p[7] = a1hi.y;
    }
    __syncthreads();
    if (w < 8) {
        const float* p = &kvsh[(size_t)(w * 32 + l) * 8];
        float inv0 = invsh[qB + qp];
        float inv1 = invsh[qB + qp + 8];
        float4 r0 = make_float4((a0lo.x + p[0]) * inv0, (a0lo.y + p[1]) * inv0,
                                (a0hi.x + p[2]) * inv0, (a0hi.y + p[3]) * inv0);
        float4 r1 = make_float4((a1lo.x + p[4]) * inv1, (a1lo.y + p[5]) * inv1,
                                (a1hi.x + p[6]) * inv1, (a1hi.y + p[7]) * inv1);
        *(float4*)&orow_base[(size_t)(qB + qp) * DKn + 4 * d4i]     = r0;
        *(float4*)&orow_base[(size_t)(qB + qp + 8) * DKn + 4 * d4i] = r1;
    }
}

// ---------------------------------------------------------------------------
extern "C" void kernel_launch(void* const* d_in, const int* in_sizes, int n_in,
                              void* d_out, int out_size) {
    const float*         Q  = (const float*)d_in[0];
    const float*         K  = (const float*)d_in[1];
    const float*         V  = (const float*)d_in[2];
    const unsigned char* Mb = (const unsigned char*)d_in[3];
    const int*           HA = (const int*)d_in[4];
    const int*           NH = (const int*)d_in[5];
    float*               O  = (float*)d_out;

    int write_w = (out_size >= (int)((size_t)BHn * TQn * (DKn + TKn))) ? 1 : 0;

    cudaFuncSetAttribute(attn_fp32x2_kernel,
                         cudaFuncAttributeMaxDynamicSharedMemorySize, SMEM_BYTES);

    detect_mask_kernel<<<1, 256>>>((const unsigned int*)Mb);

    dim3 grid(TQn / QT, BHn);
    attn_fp32x2_kernel<<<grid, NTHR, SMEM_BYTES>>>(Q, K, V, Mb, HA, NH, O, write_w);
}

// round 8
// speedup vs baseline: 1.8282x; 1.2499x over previous
#include <cuda_runtime.h>
#include <cstdint>
#include <cfloat>

#define BHn   64
#define TQn   1024
#define TKn   1024
#define DKn   64
#define QT    32      // queries per block
#define KTILE 256     // key/value tile rows staged in smem
#define NTHR  256     // 8 warps
#define KST   68      // K/V/Q row stride: 68%32=4 -> conflict-free strided f4 loads
#define SCST  1028    // score row stride: 1028%32=4

// smem layout (floats): qsh[32][68] | kvsh[256][68] | scsh[32][1028] | mbias[1024] | invsh[32]
#define QSH_F   (QT*KST)                 // 2176
#define KVSH_F  (KTILE*KST)              // 17408
#define SCSH_F  (QT*SCST)                // 32896
#define SMEM_FLOATS (QSH_F + KVSH_F + SCSH_F + TKn + 32)
#define SMEM_BYTES  (SMEM_FLOATS * 4)    // 214144 B -> 1 block/SM

// ---------------------------------------------------------------------------
__device__ int g_mask_narrow;

__global__ void detect_mask_kernel(const unsigned int* __restrict__ mw) {
    __shared__ int found;
    if (threadIdx.x == 0) found = 0;
    __syncthreads();
    int local = 0;
    for (int i = threadIdx.x; i < (BHn * TKn) / 4; i += blockDim.x) {
        if (mw[i] & 0xFFFFFF00u) local = 1;
    }
    if (local) atomicOr(&found, 1);
    __syncthreads();
    if (threadIdx.x == 0) g_mask_narrow = found;
}

// packed dual-fp32 FMA (ptxas never emits FFMA2 from C++)
__device__ __forceinline__ float2 ffma2(float2 a, float2 b, float2 c) {
    float2 d;
    asm("fma.rn.f32x2 %0, %1, %2, %3;"
        : "=l"(reinterpret_cast<unsigned long long&>(d))
        : "l"(reinterpret_cast<unsigned long long&>(a)),
          "l"(reinterpret_cast<unsigned long long&>(b)),
          "l"(reinterpret_cast<unsigned long long&>(c)));
    return d;
}

__device__ __forceinline__ unsigned int smem_u32(const void* p) {
    return (unsigned int)__cvta_generic_to_shared(p);
}
__device__ __forceinline__ void cp16(unsigned int dst, const void* src) {
    asm volatile("cp.async.cg.shared.global [%0], [%1], 16;" :: "r"(dst), "l"(src));
}
// stage one KTILE x 64 tile (256 rows x 16 float4), 16 cp.async per thread
__device__ __forceinline__ void stage_tile(unsigned int kv_u32, const float4* __restrict__ g, int t) {
    #pragma unroll
    for (int i = 0; i < 16; i++) {
        int idx = t + i * NTHR;            // 0..4095
        int r = idx >> 4, c4 = idx & 15;
        cp16(kv_u32 + (unsigned int)(r * KST + 4 * c4) * 4u, g + idx);
    }
    asm volatile("cp.async.commit_group;");
}
__device__ __forceinline__ void wait_all() {
    asm volatile("cp.async.wait_group 0;" ::: "memory");
}

// ---------------------------------------------------------------------------
// one block = 32 queries x one bh head, 8 warps
// ---------------------------------------------------------------------------
extern "C" __global__ void __launch_bounds__(NTHR, 1)
attn_fp32x2_kernel(const float* __restrict__ Q, const float* __restrict__ K,
                   const float* __restrict__ V, const unsigned char* __restrict__ Mb,
                   const int* __restrict__ pHA, const int* __restrict__ pNH,
                   float* __restrict__ Out, int write_w)
{
    extern __shared__ float sm[];
    float* qsh   = sm;                       // [QT][KST]
    float* kvsh  = sm + QSH_F;               // [KTILE][KST] (later: 8 x [32][68] partials)
    float* scsh  = kvsh + KVSH_F;            // [QT][SCST]
    float* mbias = scsh + SCSH_F;            // [1024] : 0 or -FLT_MAX
    float* invsh = mbias + TKn;              // [32]

    const int t  = threadIdx.x;
    const int w  = t >> 5;                   // warp 0..7
    const int l  = t & 31;
    const int bh = blockIdx.y;
    const int q0 = blockIdx.x * QT;

    const int nh = pNH[0];
    const int ha = pHA[0];

    float* Wout      = Out + (size_t)BHn * TQn * DKn;
    float* wrow_base = Wout + ((size_t)bh * TQn + q0) * TKn;
    float* orow_base = Out  + ((size_t)bh * TQn + q0) * DKn;

    // ---- head ablation: weights and output exactly zero ----
    if (nh > 0 && (bh % nh) == ha) {
        float4 z = make_float4(0.f, 0.f, 0.f, 0.f);
        if (write_w) {
            float4* w4 = (float4*)wrow_base;
            #pragma unroll 4
            for (int i = t; i < QT * TKn / 4; i += NTHR) w4[i] = z;
        }
        float4* o4 = (float4*)orow_base;
        #pragma unroll
        for (int i = t; i < QT * DKn / 4; i += NTHR) o4[i] = z;
        return;
    }

    const int shift = g_mask_narrow ? 0 : 2;
    const unsigned char* mrow = Mb + (((size_t)bh * TKn) << shift);

    const float4* Kg = (const float4*)(K + ((size_t)bh * TKn) * DKn);
    const float4* Vg = (const float4*)(V + ((size_t)bh * TKn) * DKn);
    const unsigned int kv_u32 = smem_u32(kvsh);

    // kick off K tile 0 immediately
    stage_tile(kv_u32, Kg, t);

    // ---- mask bias row: 0 if attended, -FLT_MAX if masked ----
    #pragma unroll
    for (int i = 0; i < 4; i++) {
        int k = t + i * NTHR;
        mbias[k] = mrow[(size_t)k << shift] ? 0.f : -FLT_MAX;
    }
    // ---- stage Q tile: 32x64 floats = 512 float4 ----
    {
        const float4* Qg = (const float4*)(Q + ((size_t)bh * TQn + q0) * DKn);
        #pragma unroll
        for (int i = 0; i < 2; i++) {
            int idx = t + i * NTHR;
            int r = idx >> 4, c4 = idx & 15;
            *(float4*)&qsh[r * KST + 4 * c4] = Qg[idx];
        }
    }

    // ================= Phase A: raw scores = QK^T =================
    // warp w owns k rows [32w, 32w+32) of each tile.
    // lane: qg=l>>3 -> q rows qg+4i (i<8); kg=l&7 -> k rows kg+8j (j<4).
    const int qg = l >> 3;
    const int kg = l & 7;

    for (int kt = 0; kt < 4; kt++) {
        wait_all();
        __syncthreads();                      // tile kt resident, prior writes done

        float2 acc[8][4];
        #pragma unroll
        for (int i = 0; i < 8; i++)
            #pragma unroll
            for (int j = 0; j < 4; j++) acc[i][j] = make_float2(0.f, 0.f);

        const float* kbasep = &kvsh[(32 * w + kg) * KST];

        #pragma unroll 4
        for (int d4 = 0; d4 < 16; d4++) {
            float4 kv[4];
            #pragma unroll
            for (int j = 0; j < 4; j++)
                kv[j] = *(const float4*)&kbasep[8 * j * KST + 4 * d4];
            #pragma unroll
            for (int i = 0; i < 8; i++) {
                float4 qv = *(const float4*)&qsh[(qg + 4 * i) * KST + 4 * d4];
                #pragma unroll
                for (int j = 0; j < 4; j++) {
                    acc[i][j] = ffma2(make_float2(qv.x, qv.y), make_float2(kv[j].x, kv[j].y), acc[i][j]);
                    acc[i][j] = ffma2(make_float2(qv.z, qv.w), make_float2(kv[j].z, kv[j].w), acc[i][j]);
                }
            }
        }

        __syncthreads();                      // all warps done reading kvsh
        // overlap: start next K tile (or V tile 0) while storing scores
        stage_tile(kv_u32, (kt < 3) ? (Kg + (size_t)(kt + 1) * KTILE * 16) : Vg, t);

        const int kb = kt * 256 + 32 * w;
        #pragma unroll
        for (int i = 0; i < 8; i++)
            #pragma unroll
            for (int j = 0; j < 4; j++)
                scsh[(qg + 4 * i) * SCST + kb + kg + 8 * j] = acc[i][j].x + acc[i][j].y;
    }
    __syncthreads();                          // scores complete (V0 still loading)

    // ================= softmax: warp w handles rows 4w..4w+3 =================
    // scale (1/8) + mask bias applied here; scsh ends up holding UNNORMALIZED exp
    #pragma unroll
    for (int rr = 0; rr < 4; rr++) {
        int r = 4 * w + rr;
        float* row = &scsh[r * SCST];

        float mx = -FLT_MAX;
        #pragma unroll
        for (int i = 0; i < 8; i++) {
            float4 x = *(const float4*)&row[4 * l + 128 * i];
            float4 b = *(const float4*)&mbias[4 * l + 128 * i];
            x.x = fmaf(x.x, 0.125f, b.x);
            x.y = fmaf(x.y, 0.125f, b.y);
            x.z = fmaf(x.z, 0.125f, b.z);
            x.w = fmaf(x.w, 0.125f, b.w);
            *(float4*)&row[4 * l + 128 * i] = x;
            mx = fmaxf(mx, fmaxf(fmaxf(x.x, x.y), fmaxf(x.z, x.w)));
        }
        #pragma unroll
        for (int off = 16; off > 0; off >>= 1)
            mx = fmaxf(mx, __shfl_xor_sync(0xffffffffu, mx, off));

        float s = 0.f;
        #pragma unroll
        for (int i = 0; i < 8; i++) {
            float4 x = *(const float4*)&row[4 * l + 128 * i];
            x.x = __expf(x.x - mx);
            x.y = __expf(x.y - mx);
            x.z = __expf(x.z - mx);
            x.w = __expf(x.w - mx);
            *(float4*)&row[4 * l + 128 * i] = x;
            s += (x.x + x.y) + (x.z + x.w);
        }
        #pragma unroll
        for (int off = 16; off > 0; off >>= 1)
            s += __shfl_xor_sync(0xffffffffu, s, off);

        if (l == 0) invsh[r] = (mx == -FLT_MAX) ? 0.f : __frcp_rn(s);
    }
    __syncthreads();

    // ---- coalesced weights store (normalized on the fly) ----
    if (write_w) {
        float4* w4 = (float4*)wrow_base;
        #pragma unroll
        for (int i = 0; i < 32; i++) {
            int j  = t + i * NTHR;            // 0..8191 float4 index
            int r  = j >> 8;
            int c4 = j & 255;
            float inv = invsh[r];
            float4 e = *(const float4*)&scsh[r * SCST + 4 * c4];
            e.x *= inv; e.y *= inv; e.z *= inv; e.w *= inv;
            w4[r * 256 + c4] = e;
        }
    }

    // ================= Phase B: out = E @ V (scaled by inv at the end) =======
    // warp w owns k rows [32w,32w+32) per tile (k split 8 ways, reduce at end).
    // lane: qg2=l>>3 -> q rows qg2+4i (i<8); dg=l&7 -> d floats [8dg, 8dg+8).
    const int qg2 = l >> 3;
    const int dg  = l & 7;

    float2 acc2[8][4];
    #pragma unroll
    for (int i = 0; i < 8; i++)
        #pragma unroll
        for (int c = 0; c < 4; c++) acc2[i][c] = make_float2(0.f, 0.f);

    for (int kt = 0; kt < 4; kt++) {
        wait_all();
        __syncthreads();                      // V tile kt resident

        const int kb = kt * 256 + 32 * w;
        #pragma unroll 2
        for (int g4 = 0; g4 < 8; g4++) {
            float4 v[4][2];
            #pragma unroll
            for (int kk = 0; kk < 4; kk++) {
                const float* vr = &kvsh[(32 * w + 4 * g4 + kk) * KST + 8 * dg];
                v[kk][0] = *(const float4*)&vr[0];
                v[kk][1] = *(const float4*)&vr[4];
            }
            #pragma unroll
            for (int i = 0; i < 8; i++) {
                float4 wf = *(const float4*)&scsh[(qg2 + 4 * i) * SCST + kb + 4 * g4];
                acc2[i][0] = ffma2(make_float2(wf.x, wf.x), make_float2(v[0][0].x, v[0][0].y), acc2[i][0]);
                acc2[i][1] = ffma2(make_float2(wf.x, wf.x), make_float2(v[0][0].z, v[0][0].w), acc2[i][1]);
                acc2[i][2] = ffma2(make_float2(wf.x, wf.x), make_float2(v[0][1].x, v[0][1].y), acc2[i][2]);
                acc2[i][3] = ffma2(make_float2(wf.x, wf.x), make_float2(v[0][1].z, v[0][1].w), acc2[i][3]);

                acc2[i][0] = ffma2(make_float2(wf.y, wf.y), make_float2(v[1][0].x, v[1][0].y), acc2[i][0]);
                acc2[i][1] = ffma2(make_float2(wf.y, wf.y), make_float2(v[1][0].z, v[1][0].w), acc2[i][1]);
                acc2[i][2] = ffma2(make_float2(wf.y, wf.y), make_float2(v[1][1].x, v[1][1].y), acc2[i][2]);
                acc2[i][3] = ffma2(make_float2(wf.y, wf.y), make_float2(v[1][1].z, v[1][1].w), acc2[i][3]);

                acc2[i][0] = ffma2(make_float2(wf.z, wf.z), make_float2(v[2][0].x, v[2][0].y), acc2[i][0]);
                acc2[i][1] = ffma2(make_float2(wf.z, wf.z), make_float2(v[2][0].z, v[2][0].w), acc2[i][1]);
                acc2[i][2] = ffma2(make_float2(wf.z, wf.z), make_float2(v[2][1].x, v[2][1].y), acc2[i][2]);
                acc2[i][3] = ffma2(make_float2(wf.z, wf.z), make_float2(v[2][1].z, v[2][1].w), acc2[i][3]);

                acc2[i][0] = ffma2(make_float2(wf.w, wf.w), make_float2(v[3][0].x, v[3][0].y), acc2[i][0]);
                acc2[i][1] = ffma2(make_float2(wf.w, wf.w), make_float2(v[3][0].z, v[3][0].w), acc2[i][1]);
                acc2[i][2] = ffma2(make_float2(wf.w, wf.w), make_float2(v[3][1].x, v[3][1].y), acc2[i][2]);
                acc2[i][3] = ffma2(make_float2(wf.w, wf.w), make_float2(v[3][1].z, v[3][1].w), acc2[i][3]);
            }
        }

        __syncthreads();                      // all warps done reading kvsh
        if (kt < 3) stage_tile(kv_u32, Vg + (size_t)(kt + 1) * KTILE * 16, t);
    }

    // ---- cross-warp k reduction via kvsh (8 partials of [32][68]) ----
    {
        float* part = &kvsh[w * (32 * KST)];
        #pragma unroll
        for (int i = 0; i < 8; i++) {
            float* p = &part[(qg2 + 4 * i) * KST + 8 * dg];
            *(float2*)&p[0] = acc2[i][0];
            *(float2*)&p[2] = acc2[i][1];
            *(float2*)&p[4] = acc2[i][2];
            *(float2*)&p[6] = acc2[i][3];
        }
    }
    __syncthreads();
    #pragma unroll
    for (int it = 0; it < 8; it++) {
        int idx = t + it * NTHR;              // 0..2047
        int q = idx >> 6, d = idx & 63;
        float s = 0.f;
        #pragma unroll
        for (int ww = 0; ww < 8; ww++)
            s += kvsh[ww * (32 * KST) + q * KST + d];
        orow_base[(size_t)q * DKn + d] = s * invsh[q];
    }
}

// ---------------------------------------------------------------------------
extern "C" void kernel_launch(void* const* d_in, const int* in_sizes, int n_in,
                              void* d_out, int out_size) {
    const float*         Q  = (const float*)d_in[0];
    const float*         K  = (const float*)d_in[1];
    const float*         V  = (const float*)d_in[2];
    const unsigned char* Mb = (const unsigned char*)d_in[3];
    const int*           HA = (const int*)d_in[4];
    const int*           NH = (const int*)d_in[5];
    float*               O  = (float*)d_out;

    int write_w = (out_size >= (int)((size_t)BHn * TQn * (DKn + TKn))) ? 1 : 0;

    cudaFuncSetAttribute(attn_fp32x2_kernel,
                         cudaFuncAttributeMaxDynamicSharedMemorySize, SMEM_BYTES);

    detect_mask_kernel<<<1, 256>>>((const unsigned int*)Mb);

    dim3 grid(TQn / QT, BHn);
    attn_fp32x2_kernel<<<grid, NTHR, SMEM_BYTES>>>(Q, K, V, Mb, HA, NH, O, write_w);
}